// round 1
// baseline (speedup 1.0000x reference)
#include <cuda_runtime.h>
#include <math.h>

#define B_DIM 1024
#define T_DIM 256
#define C_DIM 512
#define H_DIM 64
#define MROWS (B_DIM * T_DIM)   // 262144

// Scratch for projected Q, K, V  (64 MB each) — __device__ globals, no allocation.
__device__ float g_q[MROWS * H_DIM];
__device__ float g_k[MROWS * H_DIM];
__device__ float g_v[MROWS * H_DIM];

// ---------------------------------------------------------------------------
// Kernel 1: QKV projection.  Y = X @ W,  X: [M, 512] row-major, W: [512, 64].
// Tile: BM=128, BN=64, BK=16. 256 threads, 8x4 micro-tile per thread.
// grid = (3, M/128): blockIdx.x selects {Wq, Wk, Wv} (fastest -> L2 reuse of X).
// ---------------------------------------------------------------------------
#define PBM 128
#define PBK 16
#define PBN 64
#define ASTR 20   // padded row stride for As (floats)

__global__ __launch_bounds__(256) void proj_kernel(
    const float* __restrict__ x,
    const float* __restrict__ Wq,
    const float* __restrict__ Wk,
    const float* __restrict__ Wv)
{
    __shared__ __align__(16) float As[PBM * ASTR];   // [m][k], stride 20
    __shared__ __align__(16) float Bs[PBK * PBN];    // [k][n]

    const int which = blockIdx.x;
    const float* __restrict__ W = (which == 0) ? Wq : (which == 1) ? Wk : Wv;
    float* __restrict__ Y = (which == 0) ? g_q : (which == 1) ? g_k : g_v;

    const int mbase = blockIdx.y * PBM;
    const int tid = threadIdx.x;
    const int m0 = (tid >> 4) << 3;   // (tid/16)*8
    const int n0 = (tid & 15) << 2;   // (tid%16)*4

    float acc[8][4];
#pragma unroll
    for (int i = 0; i < 8; ++i)
#pragma unroll
        for (int j = 0; j < 4; ++j) acc[i][j] = 0.0f;

    for (int k0 = 0; k0 < C_DIM; k0 += PBK) {
        // Load A tile: 128 rows x 16 cols = 512 float4, 2 per thread (coalesced).
#pragma unroll
        for (int s = 0; s < 2; ++s) {
            int f = tid + s * 256;        // 0..511
            int arow = f >> 2;
            int ac4 = f & 3;
            float4 v4 = *reinterpret_cast<const float4*>(
                &x[(size_t)(mbase + arow) * C_DIM + k0 + ac4 * 4]);
            *reinterpret_cast<float4*>(&As[arow * ASTR + ac4 * 4]) = v4;
        }
        // Load B tile: 16 x 64 = 256 float4, 1 per thread (coalesced).
        {
            int krow = tid >> 4;
            int nc4 = tid & 15;
            *reinterpret_cast<float4*>(&Bs[krow * PBN + nc4 * 4]) =
                *reinterpret_cast<const float4*>(&W[(size_t)(k0 + krow) * H_DIM + nc4 * 4]);
        }
        __syncthreads();

#pragma unroll
        for (int kk = 0; kk < PBK; ++kk) {
            float a[8];
#pragma unroll
            for (int i = 0; i < 8; ++i) a[i] = As[(m0 + i) * ASTR + kk];  // warp-broadcast
            float4 b4 = *reinterpret_cast<const float4*>(&Bs[kk * PBN + n0]);
            float b[4] = {b4.x, b4.y, b4.z, b4.w};
#pragma unroll
            for (int i = 0; i < 8; ++i)
#pragma unroll
                for (int j = 0; j < 4; ++j) acc[i][j] += a[i] * b[j];
        }
        __syncthreads();
    }

#pragma unroll
    for (int i = 0; i < 8; ++i) {
        float4 o;
        o.x = acc[i][0]; o.y = acc[i][1]; o.z = acc[i][2]; o.w = acc[i][3];
        *reinterpret_cast<float4*>(&Y[(size_t)(mbase + m0 + i) * H_DIM + n0]) = o;
    }
}

// ---------------------------------------------------------------------------
// Kernel 2: causal attention, one CTA per batch.
// K, V, Q-tile (64 rows), score tile S all resident in shared memory.
//   Ks: [256][65]  (stride 65: 65 = 1 mod 32 -> strided row reads conflict-free)
//   Vs: [256][64]  (float4-friendly)
//   S : [64][260]
//   Qt: [64][68]
// 4 query tiles of 64 rows; causal structure skips key tiles beyond diagonal.
// ---------------------------------------------------------------------------
#define KS_STR 65
#define S_STR 260
#define QT_STR 68
#define SMEM_FLOATS (T_DIM * KS_STR + T_DIM * H_DIM + 64 * S_STR + 64 * QT_STR)
// = 16640 + 16384 + 16640 + 4352 = 54016 floats = 216064 bytes

extern __shared__ float sm_dyn[];

__global__ __launch_bounds__(256) void attn_kernel(float* __restrict__ out)
{
    float* Ks = sm_dyn;
    float* Vs = Ks + T_DIM * KS_STR;
    float* S  = Vs + T_DIM * H_DIM;
    float* Qt = S + 64 * S_STR;
    __shared__ float rowsum[64];

    const int b = blockIdx.x;
    const int tid = threadIdx.x;
    const int lane = tid & 31;
    const size_t base = (size_t)b * T_DIM * H_DIM;

    // Stage K (scalar stores: stride-65 rows) and V (float4) — coalesced global reads.
    for (int f = tid; f < (T_DIM * H_DIM) / 4; f += 256) {   // 4096 float4 each
        int j = f >> 4;
        int h4 = f & 15;
        float4 kv = *reinterpret_cast<const float4*>(&g_k[base + (size_t)j * H_DIM + h4 * 4]);
        float* d = &Ks[j * KS_STR + h4 * 4];
        d[0] = kv.x; d[1] = kv.y; d[2] = kv.z; d[3] = kv.w;
        float4 vv = *reinterpret_cast<const float4*>(&g_v[base + (size_t)j * H_DIM + h4 * 4]);
        *reinterpret_cast<float4*>(&Vs[j * H_DIM + h4 * 4]) = vv;
    }
    __syncthreads();

    const int m0a = (tid >> 5) << 3;   // GEMM1: warp -> 8 query rows
    const int m0b = (tid >> 4) << 2;   // GEMM2 rows
    const int n0b = (tid & 15) << 2;   // GEMM2 cols
    const int r_s = tid >> 2;          // softmax: row
    const int sub = tid & 3;           // softmax: 4 threads per row

    for (int qt = 0; qt < 4; ++qt) {
        // Stage Q tile (64 x 64), coalesced, float4 (Qt stride 68 keeps 16B align).
        for (int f = tid; f < (64 * H_DIM) / 4; f += 256) {
            int r = f >> 4;
            int h4 = f & 15;
            float4 qv = *reinterpret_cast<const float4*>(
                &g_q[base + (size_t)(qt * 64 + r) * H_DIM + h4 * 4]);
            *reinterpret_cast<float4*>(&Qt[r * QT_STR + h4 * 4]) = qv;
        }
        __syncthreads();

        // ---- GEMM1: S[64 x klim] = Qt @ Ks^T (raw scores) ----
        const int nlimj = (qt + 1) * 2;   // n = lane + 32*j < 64*(qt+1)
        float acc1[8][8];
#pragma unroll
        for (int i = 0; i < 8; ++i)
#pragma unroll
            for (int j = 0; j < 8; ++j) acc1[i][j] = 0.0f;

        for (int kk = 0; kk < H_DIM; ++kk) {
            float a[8];
#pragma unroll
            for (int i = 0; i < 8; ++i) a[i] = Qt[(m0a + i) * QT_STR + kk];  // broadcast
#pragma unroll
            for (int j = 0; j < 8; ++j) {
                if (j < nlimj) {
                    float bv = Ks[(lane + 32 * j) * KS_STR + kk];  // conflict-free
#pragma unroll
                    for (int i = 0; i < 8; ++i) acc1[i][j] += a[i] * bv;
                }
            }
        }
#pragma unroll
        for (int j = 0; j < 8; ++j) {
            if (j < nlimj) {
#pragma unroll
                for (int i = 0; i < 8; ++i)
                    S[(m0a + i) * S_STR + lane + 32 * j] = acc1[i][j];
            }
        }
        __syncthreads();

        // ---- Softmax: scale + causal mask, 4 threads per row ----
        {
            const int qrow = qt * 64 + r_s;
            const int ilim = (qt + 1) * 16;   // j = sub + 4*i covers [0, 64*(qt+1))
            float m = -1e30f;
            for (int i = 0; i < ilim; ++i) {
                int j = sub + 4 * i;
                if (j <= qrow) m = fmaxf(m, S[r_s * S_STR + j]);
            }
            m = fmaxf(m, __shfl_xor_sync(0xffffffffu, m, 1));
            m = fmaxf(m, __shfl_xor_sync(0xffffffffu, m, 2));

            float l = 0.0f;
            for (int i = 0; i < ilim; ++i) {
                int j = sub + 4 * i;
                float p = 0.0f;
                if (j <= qrow) {
                    float v = S[r_s * S_STR + j];
                    p = __expf((v - m) * 0.125f);   // scale = H^-0.5 = 1/8
                }
                S[r_s * S_STR + j] = p;
                l += p;
            }
            l += __shfl_xor_sync(0xffffffffu, l, 1);
            l += __shfl_xor_sync(0xffffffffu, l, 2);
            if (sub == 0) rowsum[r_s] = l;
        }
        __syncthreads();

        // ---- GEMM2: O[64 x 64] = P @ Vs, K-range limited by causal tile ----
        const int klim = (qt + 1) * 64;
        float acc2[4][4];
#pragma unroll
        for (int i = 0; i < 4; ++i)
#pragma unroll
            for (int j = 0; j < 4; ++j) acc2[i][j] = 0.0f;

#pragma unroll 4
        for (int kk = 0; kk < klim; ++kk) {
            float a[4];
#pragma unroll
            for (int i = 0; i < 4; ++i) a[i] = S[(m0b + i) * S_STR + kk];  // broadcast
            float4 b4 = *reinterpret_cast<const float4*>(&Vs[kk * H_DIM + n0b]);
            float bb[4] = {b4.x, b4.y, b4.z, b4.w};
#pragma unroll
            for (int i = 0; i < 4; ++i)
#pragma unroll
                for (int j = 0; j < 4; ++j) acc2[i][j] += a[i] * bb[j];
        }

#pragma unroll
        for (int i = 0; i < 4; ++i) {
            float inv = 1.0f / rowsum[m0b + i];
            float4 o;
            o.x = acc2[i][0] * inv;
            o.y = acc2[i][1] * inv;
            o.z = acc2[i][2] * inv;
            o.w = acc2[i][3] * inv;
            *reinterpret_cast<float4*>(
                &out[base + (size_t)(qt * 64 + m0b + i) * H_DIM + n0b]) = o;
        }
        __syncthreads();   // S/Qt reused next tile
    }
}

// ---------------------------------------------------------------------------
extern "C" void kernel_launch(void* const* d_in, const int* in_sizes, int n_in,
                              void* d_out, int out_size)
{
    const float* x  = (const float*)d_in[0];
    const float* Wq = (const float*)d_in[1];
    const float* Wk = (const float*)d_in[2];
    const float* Wv = (const float*)d_in[3];
    float* out = (float*)d_out;

    (void)in_sizes; (void)n_in; (void)out_size;

    // Opt-in to >48KB dynamic smem for the attention kernel (idempotent).
    cudaFuncSetAttribute(attn_kernel,
                         cudaFuncAttributeMaxDynamicSharedMemorySize,
                         SMEM_FLOATS * (int)sizeof(float));

    dim3 pgrid(3, MROWS / PBM, 1);   // head index fastest -> L2 reuse of x
    proj_kernel<<<pgrid, 256>>>(x, Wq, Wk, Wv);

    attn_kernel<<<B_DIM, 256, SMEM_FLOATS * sizeof(float)>>>(out);
}